// round 17
// baseline (speedup 1.0000x reference)
#include <cuda_runtime.h>

// LabelLoss: out[b] = sum_{n,c<7} (pred[b,n,c] - gt[b,n,c])^2
// pred, gt: [256, 16384, 8] fp32. Pure HBM-bound streaming reduction.
//
// FINAL. 268MB compulsory read at ~6.3TB/s achieved HBM bandwidth is the
// floor (verified over 16 rounds: shape/MLP/split/load-width/sync/fusion/
// L2-residency all converge to the same 43.5us bucket). Structure:
//  - grid (256 batches x 32 chunks) = 8192 blocks of 256 threads,
//    multi-wave for HW work-stealing (no slowest-SM tail)
//  - one LDG.256 per 8-channel object per stream (4 front-batched
//    256-bit non-coherent loads per thread, fully coalesced: each warp
//    instruction covers 1KB = 8 full 128B lines)
//  - channel 7 excluded by simply not using the 8th register (no mask ops)
//  - warp shuffle + smem reduction; release-atomic ticket; the last block
//    per batch row reduces the 32 partials and writes out[b] directly
//    (self-resetting counter -> graph-replay deterministic; overwrites the
//    harness's 0xAA poison without a zeroing kernel)

#define B_DIM        256
#define N_OBJ        16384
#define THREADS      256
#define SPLIT        32                       // chunks per batch row -> grid 8192
#define OBJ_PER_BLK  (N_OBJ / SPLIT)          // 512 objects per block
#define UNROLL       2                        // THREADS*UNROLL == OBJ_PER_BLK

// Partial sums [b][s]: finishing warp reads one 128B line, coalesced, L2-hit.
__device__ float g_partials[B_DIM * SPLIT];
// Ticket counters, one per batch row. Zero-initialized; self-reset each launch.
__device__ unsigned int g_count[B_DIM];

// 256-bit non-coherent load of one 8-float object (LDG.E.256).
__device__ __forceinline__ void ldg_nc_obj(const float* a, unsigned int r[8]) {
    asm volatile("ld.global.nc.v8.b32 {%0,%1,%2,%3,%4,%5,%6,%7}, [%8];"
                 : "=r"(r[0]), "=r"(r[1]), "=r"(r[2]), "=r"(r[3]),
                   "=r"(r[4]), "=r"(r[5]), "=r"(r[6]), "=r"(r[7])
                 : "l"(a));
}

__device__ __forceinline__ unsigned int atom_add_release_gpu(unsigned int* a, unsigned int v) {
    unsigned int r;
    asm volatile("atom.add.release.gpu.global.u32 %0, [%1], %2;"
                 : "=r"(r) : "l"(a), "r"(v) : "memory");
    return r;
}

__device__ __forceinline__ float ld_acquire_gpu(const float* a) {
    float r;
    asm volatile("ld.acquire.gpu.global.f32 %0, [%1];" : "=f"(r) : "l"(a) : "memory");
    return r;
}

__global__ __launch_bounds__(THREADS, 8)
void label_loss_kernel(const float* __restrict__ pred,
                       const float* __restrict__ gt,
                       float* __restrict__ out) {
    const int b = blockIdx.x;
    const int s = blockIdx.y;

    // Base object for this block; consecutive lanes -> consecutive 32B objects
    // (warp covers 1KB contiguous per load instruction, fully coalesced).
    const size_t base = ((size_t)b * N_OBJ + (size_t)s * OBJ_PER_BLK) * 8;
    const float* __restrict__ p = pred + base;
    const float* __restrict__ g = gt   + base;

    // Front-batched: 2 p + 2 g = 4 LDG.256 per thread (128B/thread/stream).
    unsigned int pr[UNROLL][8], gr[UNROLL][8];
    #pragma unroll
    for (int u = 0; u < UNROLL; u++) {
        const int off = (u * THREADS + threadIdx.x) * 8;
        ldg_nc_obj(p + off, pr[u]);
        ldg_nc_obj(g + off, gr[u]);
    }

    float acc = 0.0f;
    #pragma unroll
    for (int u = 0; u < UNROLL; u++) {
        #pragma unroll
        for (int c = 0; c < 7; c++) {        // channel 7 (index 7) excluded
            float d = __uint_as_float(pr[u][c]) - __uint_as_float(gr[u][c]);
            acc += d * d;
        }
    }

    // Warp reduction
    #pragma unroll
    for (int off = 16; off > 0; off >>= 1)
        acc += __shfl_xor_sync(0xFFFFFFFFu, acc, off);

    // Cross-warp reduction via shared memory
    __shared__ float warp_sums[THREADS / 32];
    const int lane = threadIdx.x & 31;
    const int wid  = threadIdx.x >> 5;
    if (lane == 0) warp_sums[wid] = acc;
    __syncthreads();

    if (wid == 0) {
        float v = (lane < THREADS / 32) ? warp_sums[lane] : 0.0f;
        #pragma unroll
        for (int off = 4; off > 0; off >>= 1)
            v += __shfl_xor_sync(0xFFFFFFFFu, v, off);

        // Publish partial (plain store), then release-ticket (orders the
        // store at gpu scope without an L1-flushing fence).
        unsigned int ticket = 0;
        if (lane == 0) {
            g_partials[b * SPLIT + s] = v;
            ticket = atom_add_release_gpu(&g_count[b], 1u);
        }
        ticket = __shfl_sync(0xFFFFFFFFu, ticket, 0);

        // Last block for this batch row reduces all 32 partials.
        if (ticket == SPLIT - 1) {
            float r = ld_acquire_gpu(&g_partials[b * SPLIT + lane]);
            #pragma unroll
            for (int off = 16; off > 0; off >>= 1)
                r += __shfl_xor_sync(0xFFFFFFFFu, r, off);
            if (lane == 0) {
                out[b] = r;
                g_count[b] = 0;                      // reset for next graph replay
            }
        }
    }
}

extern "C" void kernel_launch(void* const* d_in, const int* in_sizes, int n_in,
                              void* d_out, int out_size) {
    const float* pred = (const float*)d_in[0];
    const float* gt   = (const float*)d_in[1];
    float* out        = (float*)d_out;

    dim3 grid(B_DIM, SPLIT);
    label_loss_kernel<<<grid, THREADS>>>(pred, gt, out);
}